// round 16
// baseline (speedup 1.0000x reference)
#include <cuda_runtime.h>

#define NQ 10
#define NT 64            // 2 independent warps per CTA, 1 batch element per warp
#define R  32            // amplitudes per thread (5 register bits)

typedef unsigned long long u64;

// ---- packed f32x2 helpers (sm_103a) ----
__device__ __forceinline__ u64 pack2(float x, float y) {
    u64 r; asm("mov.b64 %0, {%1,%2};" : "=l"(r) : "f"(x), "f"(y)); return r;
}
__device__ __forceinline__ void unpack2(u64 v, float& x, float& y) {
    asm("mov.b64 {%0,%1}, %2;" : "=f"(x), "=f"(y) : "l"(v));
}
__device__ __forceinline__ u64 fma2(u64 a, u64 b, u64 c) {
    u64 d; asm("fma.rn.f32x2 %0, %1, %2, %3;" : "=l"(d) : "l"(a), "l"(b), "l"(c)); return d;
}
__device__ __forceinline__ u64 mul2(u64 a, u64 b) {
    u64 d; asm("mul.rn.f32x2 %0, %1, %2;" : "=l"(d) : "l"(a), "l"(b)); return d;
}
__device__ __forceinline__ float2 cmul(float2 a, float2 b) {
    return make_float2(a.x * b.x - a.y * b.y, a.x * b.y + a.y * b.x);
}
// scalar complex multiply of a packed amp by complex m (no pair-swap MOVs:
// 2 FMUL + 2 FFMA, any-register targets)
__device__ __forceinline__ u64 cmul_s(u64 amp, float2 m) {
    float x, y; unpack2(amp, x, y);
    return pack2(x * m.x - y * m.y, x * m.y + y * m.x);
}
__device__ __forceinline__ float2 u2f(u64 v) {
    float x, y; unpack2(v, x, y);
    return make_float2(x, y);
}
// 128-bit-friendly swizzle: key(h) = 2*(h&15) (even -> u64 pairs stay adjacent
// and 16B-aligned). Conflict-free for A-store, vectorized B-load/B-store,
// and the ring gather (parity key-split = 16, congruent 0 mod 16).
__device__ __forceinline__ int keyf(int h) { return (h & 15) << 1; }

// Lifted RY on register-bit P: n0 = a0 - t*a1 ; n1 = t*a0 + a1 (scale deferred)
template<int P>
__device__ __forceinline__ void ry_lift(u64* a, u64 pt, u64 mt)
{
#pragma unroll
    for (int k = 0; k < 16; k++) {
        const int r0 = ((k >> P) << (P + 1)) | (k & ((1 << P) - 1));
        const int r1 = r0 | (1 << P);
        const u64 a0 = a[r0], a1 = a[r1];
        a[r0] = fma2(mt, a1, a0);
        a[r1] = fma2(pt, a0, a1);
    }
}

__device__ __forceinline__ float2 shfl_c(float2 v, int src) {
    return make_float2(__shfl_sync(0xffffffffu, v.x, src),
                       __shfl_sync(0xffffffffu, v.y, src));
}

__global__ __launch_bounds__(NT, 10)
void qnn_kernel(const float* __restrict__ x,      // (B, 10)
                const float* __restrict__ w,      // (3, 10, 3)
                float* __restrict__ out)          // (B, 10)
{
    __shared__ __align__(16) u64 st[2][1024];     // per-warp exchange buffer
    __shared__ __align__(16) u64 ryk[2][2][NQ][2];   // gate consts (pt,mt) pairs
    __shared__ __align__(16) u64 TIp[2][2][R + 2];   // init table, packed value
    __shared__ __align__(16) u64 TTp[2][2][R + 2];   // ring-diag table, packed value

    const int lane = threadIdx.x & 31;
    const int wid  = threadIdx.x >> 5;
    const int b    = blockIdx.x * 2 + wid;

    // setup-only tables overlaid into the st exchange buffer (dead before
    // the first transpose write): vcol 20, eg 20, ea 10 float2 entries
    float2* vcolw = reinterpret_cast<float2*>(&st[wid][0]);    // [q*2+j]
    float2* egw   = reinterpret_cast<float2*>(&st[wid][20]);   // [l*10+q]
    float2* eaw   = reinterpret_cast<float2*>(&st[wid][40]);   // [q]

    // ---- stage 1: fused gates + ZYZ (lanes 0..29 of each warp) ----
    float myf = 1.f;                              // deferred lifted-scale factor
    if (lane < 30) {
        const int q = lane % NQ;
        const float xv  = x[b * NQ + q];
        const float phi = w[lane * 3 + 0];
        const float th  = w[lane * 3 + 1];
        const float om  = w[lane * 3 + 2];
        float s, c;   sincosf(0.5f * xv, &s, &c);
        float sh, ch; sincosf(0.5f * th, &sh, &ch);
        float sa, ca; sincosf(0.5f * (phi + om), &sa, &ca);
        float sb, cb; sincosf(0.5f * (phi - om), &sb, &cb);
        const float m00x =  ca * ch, m00y = -sa * ch;
        const float m01x = -cb * sh, m01y = -sb * sh;
        const float m10x =  cb * sh, m10y = -sb * sh;
        const float m11x =  ca * ch, m11y =  sa * ch;
        const float g00x =  m00x * c + m01x * s, g00y =  m00y * c + m01y * s;
        const float g10x =  m10x * c + m11x * s, g10y =  m10y * c + m11y * s;
        if (lane < NQ) {
            vcolw[q * 2 + 0] = make_float2(g00x, g00y);
            vcolw[q * 2 + 1] = make_float2(g10x, g10y);
        } else {
            const int l = lane / NQ - 1;
            const float cc = sqrtf(g00x * g00x + g00y * g00y);
            const float ss = sqrtf(g10x * g10x + g10y * g10y);
            float2 uA, uB;
            if (cc > 0.f) { const float iv = 1.f / cc; uA = make_float2(g00x * iv, -g00y * iv); }
            else uA = make_float2(1.f, 0.f);
            if (ss > 0.f) { const float iv = 1.f / ss; uB = make_float2(g10x * iv,  g10y * iv); }
            else uB = make_float2(1.f, 0.f);
            const float ccg = fmaxf(cc, 1e-30f);
            const float t   = ss / ccg;
            myf = ccg;
            ryk[wid][l][q][0] = pack2(t, t);
            ryk[wid][l][q][1] = pack2(-t, -t);
            egw[l * NQ + q] = cmul(uA, make_float2(uB.x, -uB.y));
            if (l == 0) eaw[q] = cmul(uA, uB);
        }
    }
    __syncwarp();
    float Z = myf;                                // product of 20 scale factors
#pragma unroll
    for (int o = 16; o > 0; o >>= 1) Z *= __shfl_xor_sync(0xffffffffu, Z, o);
    const float Zsq = Z * Z;

    // ---- stage 2: per-bit product tables, register-resident (entry h = lane) ----
    float2 rt0, eh, tA1v, tA2v;
    {
        const int h = lane;
        float2 v = vcolw[4 * 2 + (h & 1)];
        v = cmul(v, vcolw[3 * 2 + ((h >> 1) & 1)]);
        v = cmul(v, vcolw[2 * 2 + ((h >> 2) & 1)]);
        v = cmul(v, vcolw[1 * 2 + ((h >> 3) & 1)]);
        v = cmul(v, vcolw[0 * 2 + ((h >> 4) & 1)]);
        rt0 = v;
        float2 a1 = make_float2(1.f, 0.f), a2 = a1, e = a1;
#pragma unroll
        for (int j = 0; j < 5; j++)
            if ((h >> j) & 1) {
                a1 = cmul(a1, egw[0 * NQ + 4 - j]);
                a2 = cmul(a2, egw[1 * NQ + 4 - j]);
                e  = cmul(e,  eaw[4 - j]);
            }
        tA1v = a1;  tA2v = a2;  eh = e;
    }
    __syncwarp();

    // ---- stage 3: combined tables via shfl (parity p = src-lane lsb) ----
    {
        const int h   = lane;
        const int sh0 = h ^ (h >> 1);
        const int sh1 = sh0 ^ 0b11000;
        const float2 r0 = shfl_c(rt0, sh0), r1 = shfl_c(rt0, sh1);
        const float2 e0 = shfl_c(eh,  sh0), e1 = shfl_c(eh,  sh1);
        const float2 ti0 = cmul(r0, tA1v), ti1 = cmul(r1, tA1v);
        const float2 tt0 = cmul(e0, tA2v), tt1 = cmul(e1, tA2v);
        TIp[wid][0][h] = pack2(ti0.x, ti0.y);
        TIp[wid][1][h] = pack2(ti1.x, ti1.y);
        TTp[wid][0][h] = pack2(tt0.x, tt0.y);
        TTp[wid][1][h] = pack2(tt1.x, tt1.y);
    }
    // ---- per-thread scalars ----
    float2 sgam1 = make_float2(1.f, 0.f), sgam2 = sgam1;
#pragma unroll
    for (int k = 0; k < 5; k++)
        if ((lane >> k) & 1) {
            sgam1 = cmul(sgam1, egw[0 * NQ + 9 - k]);
            sgam2 = cmul(sgam2, egw[1 * NQ + 9 - k]);
        }
    const int m0 = lane ^ (lane >> 1);
    float2 el = make_float2(1.f, 0.f);
#pragma unroll
    for (int j = 0; j < 5; j++)
        if ((m0 >> j) & 1) el = cmul(el, eaw[9 - j]);
    const float2 el2 = ((m0 >> 4) & 1)
        ? cmul(el, make_float2(eaw[5].x, -eaw[5].y))
        : cmul(el, eaw[5]);
    const float2 SL0f = cmul(el,  sgam2);         // SL for even r
    const float2 SL1f = cmul(el2, sgam2);         // SL for odd r
    // init lane scalars (layer-0 lane part at the two src_lo values, sgam1 folded)
    float2 lp = vcolw[9 * 2 + (m0 & 1)];
    lp = cmul(lp, vcolw[8 * 2 + ((m0 >> 1) & 1)]);
    lp = cmul(lp, vcolw[7 * 2 + ((m0 >> 2) & 1)]);
    lp = cmul(lp, vcolw[6 * 2 + ((m0 >> 3) & 1)]);
    const int b4 = (m0 >> 4) & 1;
    const float2 l0 = cmul(cmul(lp, vcolw[5 * 2 + b4]),       sgam1);  // even r
    const float2 l1 = cmul(cmul(lp, vcolw[5 * 2 + (1 - b4)]), sgam1);  // odd r
    __syncwarp();

    const int pl2 = lane & 1;
    const u64* TIq = TIp[wid][pl2];
    const u64* TTq = TTp[wid][pl2];
    u64* S = st[wid];
    const int kl = keyf(lane);                    // even, per-lane swizzle key

    // ---- init: layer-0 product state + ring-0 + Dgamma(1), layout A ----
    // a[r] = TI[p][r] * l_{r&1}  (vectorized table fetch, scalar complex mul)
    u64 a[R];
#pragma unroll
    for (int k = 0; k < 16; k++) {
        const ulonglong2 tv = *reinterpret_cast<const ulonglong2*>(&TIq[2 * k]);
        a[2 * k]     = cmul_s(tv.x, l0);
        a[2 * k + 1] = cmul_s(tv.y, l1);
    }

    // ---- layers 1, 2 (lifted RY; diagonals pre-combined) ----
#pragma unroll 1
    for (int l = 0; l < 2; l++) {
        // layout A: qubits 0..4 on reg bits 4..0 (gate consts: one LDS.128 each)
        {
            const ulonglong2 g0 = *reinterpret_cast<const ulonglong2*>(&ryk[wid][l][0][0]);
            ry_lift<4>(a, g0.x, g0.y);
            const ulonglong2 g1 = *reinterpret_cast<const ulonglong2*>(&ryk[wid][l][1][0]);
            ry_lift<3>(a, g1.x, g1.y);
            const ulonglong2 g2 = *reinterpret_cast<const ulonglong2*>(&ryk[wid][l][2][0]);
            ry_lift<2>(a, g2.x, g2.y);
            const ulonglong2 g3 = *reinterpret_cast<const ulonglong2*>(&ryk[wid][l][3][0]);
            ry_lift<1>(a, g3.x, g3.y);
            const ulonglong2 g4 = *reinterpret_cast<const ulonglong2*>(&ryk[wid][l][4][0]);
            ry_lift<0>(a, g4.x, g4.y);
        }

        // transpose A -> B: scalar A-pattern stores, vector B-pattern loads
#pragma unroll
        for (int r = 0; r < R; r++)
            S[((r << 5) | lane) ^ keyf(r)] = a[r];   // keyf(r) compile-time
        __syncwarp();
#pragma unroll
        for (int k = 0; k < 16; k++) {
            const int idx = (lane << 5) | ((2 * k) ^ kl);
            const ulonglong2 v = *reinterpret_cast<const ulonglong2*>(&S[idx]);
            a[2 * k]     = v.x;
            a[2 * k + 1] = v.y;
        }
        __syncwarp();

        // layout B: qubits 5..9 on reg bits 4..0
        {
            const ulonglong2 g5 = *reinterpret_cast<const ulonglong2*>(&ryk[wid][l][5][0]);
            ry_lift<4>(a, g5.x, g5.y);
            const ulonglong2 g6 = *reinterpret_cast<const ulonglong2*>(&ryk[wid][l][6][0]);
            ry_lift<3>(a, g6.x, g6.y);
            const ulonglong2 g7 = *reinterpret_cast<const ulonglong2*>(&ryk[wid][l][7][0]);
            ry_lift<2>(a, g7.x, g7.y);
            const ulonglong2 g8 = *reinterpret_cast<const ulonglong2*>(&ryk[wid][l][8][0]);
            ry_lift<1>(a, g8.x, g8.y);
            const ulonglong2 g9 = *reinterpret_cast<const ulonglong2*>(&ryk[wid][l][9][0]);
            ry_lift<0>(a, g9.x, g9.y);
        }

        if (l == 0) {
            // ring gather with Dalpha(1)[src] * Dgamma(2)[dst] fused,
            // scalar complex multiplies (no pair-swap MOVs)
#pragma unroll
            for (int k = 0; k < 16; k++) {
                const int idx = (lane << 5) | ((2 * k) ^ kl);
                *reinterpret_cast<ulonglong2*>(&S[idx]) =
                    make_ulonglong2(a[2 * k], a[2 * k + 1]);
            }
            __syncwarp();
#pragma unroll
            for (int k = 0; k < 16; k++) {
                const ulonglong2 tv = *reinterpret_cast<const ulonglong2*>(&TTq[2 * k]);
                const int j0 = ((2 * k) << 5) | lane;
                int src0 = j0 ^ (j0 >> 1);
                const int j1 = j0 | 32;           // r = 2k+1
                int src1 = j1 ^ (j1 >> 1);
                if (lane & 1) { src0 ^= 0x300; src1 ^= 0x300; }
                const u64 raw0 = S[src0 ^ keyf(src0 >> 5)];
                const u64 raw1 = S[src1 ^ keyf(src1 >> 5)];
                a[2 * k]     = cmul_s(cmul_s(raw0, u2f(tv.x)), SL0f);
                a[2 * k + 1] = cmul_s(cmul_s(raw1, u2f(tv.y)), SL1f);
            }
            __syncwarp();
        }
        // layer 2: Dalpha(2) dropped (diagonal before measurement)
    }

    // ---- readout in layout B, final ring folded into parity signs ----
    float T = 0.f, P0 = 0.f, P1 = 0.f, P2 = 0.f, P3 = 0.f, P4 = 0.f;
#pragma unroll
    for (int r = 0; r < R; r++) {
        float xx, yy; unpack2(mul2(a[r], a[r]), xx, yy);
        const float p = xx + yy;
        T  += p;
        P0 += (__popc(r)      & 1) ? -p : p;
        P1 += (__popc(r >> 1) & 1) ? -p : p;
        P2 += (__popc(r >> 2) & 1) ? -p : p;
        P3 += (__popc(r >> 3) & 1) ? -p : p;
        P4 += (__popc(r >> 4) & 1) ? -p : p;
    }

    const int pl = __popc(lane) & 1;
    float z[NQ];
    z[9] = pl ? -P0 : P0;
    z[8] = pl ? -P1 : P1;
    z[7] = pl ? -P2 : P2;
    z[6] = pl ? -P3 : P3;
    z[5] = pl ? -P4 : P4;
    z[4] = pl ? -T  : T;
    z[3] = (__popc(lane >> 1) & 1) ? -T : T;
    z[2] = (__popc(lane >> 2) & 1) ? -T : T;
    z[1] = (__popc(lane >> 3) & 1) ? -T : T;
    z[0] = (__popc(lane & 0xF) & 1) ? -P0 : P0;

#pragma unroll
    for (int q = 0; q < NQ; q++) {
#pragma unroll
        for (int o = 16; o > 0; o >>= 1)
            z[q] += __shfl_xor_sync(0xffffffffu, z[q], o);
    }
    if (lane == 0) {
#pragma unroll
        for (int q = 0; q < NQ; q++) out[b * NQ + q] = z[q] * Zsq;
    }
}

extern "C" void kernel_launch(void* const* d_in, const int* in_sizes, int n_in,
                              void* d_out, int out_size)
{
    const float* x = (const float*)d_in[0];       // (B, 10) float32
    const float* w = (const float*)d_in[1];       // (3, 10, 3) float32
    float* out = (float*)d_out;                   // (B, 10) float32
    const int B = in_sizes[0] / NQ;
    qnn_kernel<<<B / 2, NT>>>(x, w, out);
}

// round 17
// speedup vs baseline: 1.1115x; 1.1115x over previous
#include <cuda_runtime.h>

#define NQ 10
#define NT 64            // 2 independent warps per CTA, 1 batch element per warp
#define R  32            // amplitudes per thread (5 register bits)

typedef unsigned long long u64;

// ---- packed f32x2 helpers (sm_103a) ----
__device__ __forceinline__ u64 pack2(float x, float y) {
    u64 r; asm("mov.b64 %0, {%1,%2};" : "=l"(r) : "f"(x), "f"(y)); return r;
}
__device__ __forceinline__ void unpack2(u64 v, float& x, float& y) {
    asm("mov.b64 {%0,%1}, %2;" : "=f"(x), "=f"(y) : "l"(v));
}
__device__ __forceinline__ u64 swap2(u64 v) {
    float x, y; unpack2(v, x, y); return pack2(y, x);
}
__device__ __forceinline__ u64 fma2(u64 a, u64 b, u64 c) {
    u64 d; asm("fma.rn.f32x2 %0, %1, %2, %3;" : "=l"(d) : "l"(a), "l"(b), "l"(c)); return d;
}
__device__ __forceinline__ u64 mul2(u64 a, u64 b) {
    u64 d; asm("mul.rn.f32x2 %0, %1, %2;" : "=l"(d) : "l"(a), "l"(b)); return d;
}
__device__ __forceinline__ float2 cmul(float2 a, float2 b) {
    return make_float2(a.x * b.x - a.y * b.y, a.x * b.y + a.y * b.x);
}
// amp *= m, with m pre-dup'd as mxx=(m.x,m.x), myy=(-m.y,m.y)
__device__ __forceinline__ u64 dmul(u64 amp, u64 mxx, u64 myy) {
    return fma2(mxx, amp, mul2(myy, swap2(amp)));
}
// 128-bit-friendly swizzle: key(h) = 2*(h&15) (even -> u64 pairs stay adjacent
// and 16B-aligned). Conflict-free for A-store, vectorized B-load/B-store,
// and the ring gather (parity key-split = 16, congruent 0 mod 16).
__device__ __forceinline__ int keyf(int h) { return (h & 15) << 1; }

// Lifted RY on register-bit P: n0 = a0 - t*a1 ; n1 = t*a0 + a1 (scale deferred)
template<int P>
__device__ __forceinline__ void ry_lift(u64* a, u64 pt, u64 mt)
{
#pragma unroll
    for (int k = 0; k < 16; k++) {
        const int r0 = ((k >> P) << (P + 1)) | (k & ((1 << P) - 1));
        const int r1 = r0 | (1 << P);
        const u64 a0 = a[r0], a1 = a[r1];
        a[r0] = fma2(mt, a1, a0);
        a[r1] = fma2(pt, a0, a1);
    }
}

__device__ __forceinline__ float2 shfl_c(float2 v, int src) {
    return make_float2(__shfl_sync(0xffffffffu, v.x, src),
                       __shfl_sync(0xffffffffu, v.y, src));
}

__global__ __launch_bounds__(NT, 10)
void qnn_kernel(const float* __restrict__ x,      // (B, 10)
                const float* __restrict__ w,      // (3, 10, 3)
                float* __restrict__ out)          // (B, 10)
{
    __shared__ __align__(16) u64 st[2][1024];     // per-warp exchange buffer
    __shared__ __align__(16) u64 ryk[2][2][NQ][2];   // gate consts (pt,mt) pairs
    __shared__ u64 TIp[2][2][R + 2];              // init table (padded)
    __shared__ __align__(16) u64 TT[2][2][R + 1][2]; // ring-diag (xx,yy) interleaved

    const int lane = threadIdx.x & 31;
    const int wid  = threadIdx.x >> 5;
    const int b    = blockIdx.x * 2 + wid;

    // setup-only tables overlaid into the st exchange buffer (dead before
    // the first transpose write): vcol 20, eg 20, ea 10 float2 entries
    float2* vcolw = reinterpret_cast<float2*>(&st[wid][0]);    // [q*2+j]
    float2* egw   = reinterpret_cast<float2*>(&st[wid][20]);   // [l*10+q]
    float2* eaw   = reinterpret_cast<float2*>(&st[wid][40]);   // [q]

    // ---- stage 1: fused gates + ZYZ (lanes 0..29 of each warp) ----
    float myf = 1.f;                              // deferred lifted-scale factor
    if (lane < 30) {
        const int q = lane % NQ;
        const float xv  = x[b * NQ + q];
        const float phi = w[lane * 3 + 0];
        const float th  = w[lane * 3 + 1];
        const float om  = w[lane * 3 + 2];
        float s, c;   sincosf(0.5f * xv, &s, &c);
        float sh, ch; sincosf(0.5f * th, &sh, &ch);
        float sa, ca; sincosf(0.5f * (phi + om), &sa, &ca);
        float sb, cb; sincosf(0.5f * (phi - om), &sb, &cb);
        const float m00x =  ca * ch, m00y = -sa * ch;
        const float m01x = -cb * sh, m01y = -sb * sh;
        const float m10x =  cb * sh, m10y = -sb * sh;
        const float m11x =  ca * ch, m11y =  sa * ch;
        const float g00x =  m00x * c + m01x * s, g00y =  m00y * c + m01y * s;
        const float g10x =  m10x * c + m11x * s, g10y =  m10y * c + m11y * s;
        if (lane < NQ) {
            vcolw[q * 2 + 0] = make_float2(g00x, g00y);
            vcolw[q * 2 + 1] = make_float2(g10x, g10y);
        } else {
            const int l = lane / NQ - 1;
            const float cc = sqrtf(g00x * g00x + g00y * g00y);
            const float ss = sqrtf(g10x * g10x + g10y * g10y);
            float2 uA, uB;
            if (cc > 0.f) { const float iv = 1.f / cc; uA = make_float2(g00x * iv, -g00y * iv); }
            else uA = make_float2(1.f, 0.f);
            if (ss > 0.f) { const float iv = 1.f / ss; uB = make_float2(g10x * iv,  g10y * iv); }
            else uB = make_float2(1.f, 0.f);
            const float ccg = fmaxf(cc, 1e-30f);
            const float t   = ss / ccg;
            myf = ccg;
            ryk[wid][l][q][0] = pack2(t, t);
            ryk[wid][l][q][1] = pack2(-t, -t);
            egw[l * NQ + q] = cmul(uA, make_float2(uB.x, -uB.y));
            if (l == 0) eaw[q] = cmul(uA, uB);
        }
    }
    __syncwarp();
    float Z = myf;                                // product of 20 scale factors
#pragma unroll
    for (int o = 16; o > 0; o >>= 1) Z *= __shfl_xor_sync(0xffffffffu, Z, o);
    const float Zsq = Z * Z;

    // ---- stage 2: per-bit product tables, register-resident (entry h = lane) ----
    float2 rt0, eh, tA1v, tA2v;
    {
        const int h = lane;
        float2 v = vcolw[4 * 2 + (h & 1)];
        v = cmul(v, vcolw[3 * 2 + ((h >> 1) & 1)]);
        v = cmul(v, vcolw[2 * 2 + ((h >> 2) & 1)]);
        v = cmul(v, vcolw[1 * 2 + ((h >> 3) & 1)]);
        v = cmul(v, vcolw[0 * 2 + ((h >> 4) & 1)]);
        rt0 = v;
        float2 a1 = make_float2(1.f, 0.f), a2 = a1, e = a1;
#pragma unroll
        for (int j = 0; j < 5; j++)
            if ((h >> j) & 1) {
                a1 = cmul(a1, egw[0 * NQ + 4 - j]);
                a2 = cmul(a2, egw[1 * NQ + 4 - j]);
                e  = cmul(e,  eaw[4 - j]);
            }
        tA1v = a1;  tA2v = a2;  eh = e;
    }
    __syncwarp();

    // ---- stage 3: combined tables via shfl (parity p = src-lane lsb) ----
    {
        const int h   = lane;
        const int sh0 = h ^ (h >> 1);
        const int sh1 = sh0 ^ 0b11000;
        const float2 r0 = shfl_c(rt0, sh0), r1 = shfl_c(rt0, sh1);
        const float2 e0 = shfl_c(eh,  sh0), e1 = shfl_c(eh,  sh1);
        const float2 ti0 = cmul(r0, tA1v), ti1 = cmul(r1, tA1v);
        const float2 tt0 = cmul(e0, tA2v), tt1 = cmul(e1, tA2v);
        TIp[wid][0][h] = pack2(ti0.x, ti0.y);
        TIp[wid][1][h] = pack2(ti1.x, ti1.y);
        *reinterpret_cast<ulonglong2*>(&TT[wid][0][h][0]) =
            make_ulonglong2(pack2(tt0.x, tt0.x), pack2(-tt0.y, tt0.y));
        *reinterpret_cast<ulonglong2*>(&TT[wid][1][h][0]) =
            make_ulonglong2(pack2(tt1.x, tt1.x), pack2(-tt1.y, tt1.y));
    }
    // ---- per-thread scalars ----
    float2 sgam1 = make_float2(1.f, 0.f), sgam2 = sgam1;
#pragma unroll
    for (int k = 0; k < 5; k++)
        if ((lane >> k) & 1) {
            sgam1 = cmul(sgam1, egw[0 * NQ + 9 - k]);
            sgam2 = cmul(sgam2, egw[1 * NQ + 9 - k]);
        }
    const int m0 = lane ^ (lane >> 1);
    float2 el = make_float2(1.f, 0.f);
#pragma unroll
    for (int j = 0; j < 5; j++)
        if ((m0 >> j) & 1) el = cmul(el, eaw[9 - j]);
    const float2 el2 = ((m0 >> 4) & 1)
        ? cmul(el, make_float2(eaw[5].x, -eaw[5].y))
        : cmul(el, eaw[5]);
    const float2 SL0f = cmul(el,  sgam2);
    const float2 SL1f = cmul(el2, sgam2);
    const u64 SLx0 = pack2(SL0f.x, SL0f.x), SLy0 = pack2(-SL0f.y, SL0f.y);
    const u64 SLx1 = pack2(SL1f.x, SL1f.x), SLy1 = pack2(-SL1f.y, SL1f.y);
    // init lane scalars (layer-0 lane part at the two src_lo values, sgam1 folded)
    float2 lp = vcolw[9 * 2 + (m0 & 1)];
    lp = cmul(lp, vcolw[8 * 2 + ((m0 >> 1) & 1)]);
    lp = cmul(lp, vcolw[7 * 2 + ((m0 >> 2) & 1)]);
    lp = cmul(lp, vcolw[6 * 2 + ((m0 >> 3) & 1)]);
    const int b4 = (m0 >> 4) & 1;
    const float2 l0 = cmul(cmul(lp, vcolw[5 * 2 + b4]),       sgam1);
    const float2 l1 = cmul(cmul(lp, vcolw[5 * 2 + (1 - b4)]), sgam1);
    const u64 ls0xx = pack2(l0.x, l0.x), ls0yy = pack2(-l0.y, l0.y);
    const u64 ls1xx = pack2(l1.x, l1.x), ls1yy = pack2(-l1.y, l1.y);
    __syncwarp();

    const int pl2 = lane & 1;
    const u64* TIq = TIp[wid][pl2];
    const u64 (*TTq)[2] = TT[wid][pl2];
    u64* S = st[wid];
    const int kl = keyf(lane);                    // even, per-lane swizzle key

    // ---- init: layer-0 product state + ring-0 + Dgamma(1), layout A ----
    u64 a[R];
#pragma unroll
    for (int r = 0; r < R; r++)
        a[r] = (r & 1) ? dmul(TIq[r], ls1xx, ls1yy)
                       : dmul(TIq[r], ls0xx, ls0yy);

    // ---- layers 1, 2 (lifted RY; diagonals pre-combined) ----
#pragma unroll 1
    for (int l = 0; l < 2; l++) {
        // layout A: qubits 0..4 on reg bits 4..0 (gate consts: one LDS.128 each)
        {
            const ulonglong2 g0 = *reinterpret_cast<const ulonglong2*>(&ryk[wid][l][0][0]);
            ry_lift<4>(a, g0.x, g0.y);
            const ulonglong2 g1 = *reinterpret_cast<const ulonglong2*>(&ryk[wid][l][1][0]);
            ry_lift<3>(a, g1.x, g1.y);
            const ulonglong2 g2 = *reinterpret_cast<const ulonglong2*>(&ryk[wid][l][2][0]);
            ry_lift<2>(a, g2.x, g2.y);
            const ulonglong2 g3 = *reinterpret_cast<const ulonglong2*>(&ryk[wid][l][3][0]);
            ry_lift<1>(a, g3.x, g3.y);
            const ulonglong2 g4 = *reinterpret_cast<const ulonglong2*>(&ryk[wid][l][4][0]);
            ry_lift<0>(a, g4.x, g4.y);
        }

        // transpose A -> B: scalar A-pattern stores, vector B-pattern loads
#pragma unroll
        for (int r = 0; r < R; r++)
            S[((r << 5) | lane) ^ keyf(r)] = a[r];   // keyf(r) compile-time
        __syncwarp();
#pragma unroll
        for (int k = 0; k < 16; k++) {
            const int idx = (lane << 5) | ((2 * k) ^ kl);
            const ulonglong2 v = *reinterpret_cast<const ulonglong2*>(&S[idx]);
            a[2 * k]     = v.x;
            a[2 * k + 1] = v.y;
        }
        __syncwarp();

        // layout B: qubits 5..9 on reg bits 4..0
        {
            const ulonglong2 g5 = *reinterpret_cast<const ulonglong2*>(&ryk[wid][l][5][0]);
            ry_lift<4>(a, g5.x, g5.y);
            const ulonglong2 g6 = *reinterpret_cast<const ulonglong2*>(&ryk[wid][l][6][0]);
            ry_lift<3>(a, g6.x, g6.y);
            const ulonglong2 g7 = *reinterpret_cast<const ulonglong2*>(&ryk[wid][l][7][0]);
            ry_lift<2>(a, g7.x, g7.y);
            const ulonglong2 g8 = *reinterpret_cast<const ulonglong2*>(&ryk[wid][l][8][0]);
            ry_lift<1>(a, g8.x, g8.y);
            const ulonglong2 g9 = *reinterpret_cast<const ulonglong2*>(&ryk[wid][l][9][0]);
            ry_lift<0>(a, g9.x, g9.y);
        }

        if (l == 0) {
            // ring gather with Dalpha(1)[src] * Dgamma(2)[dst] fused
#pragma unroll
            for (int k = 0; k < 16; k++) {
                const int idx = (lane << 5) | ((2 * k) ^ kl);
                *reinterpret_cast<ulonglong2*>(&S[idx]) =
                    make_ulonglong2(a[2 * k], a[2 * k + 1]);
            }
            __syncwarp();
#pragma unroll
            for (int r = 0; r < R; r++) {
                const int j = (r << 5) | lane;
                int src = j ^ (j >> 1);
                if (lane & 1) src ^= 0x300;
                const u64 raw = S[src ^ keyf(src >> 5)];
                const ulonglong2 tv = *reinterpret_cast<const ulonglong2*>(&TTq[r][0]);
                const u64 t1 = dmul(raw, tv.x, tv.y);
                a[r] = (r & 1) ? dmul(t1, SLx1, SLy1) : dmul(t1, SLx0, SLy0);
            }
            __syncwarp();
        }
        // layer 2: Dalpha(2) dropped (diagonal before measurement)
    }

    // ---- readout in layout B, final ring folded into parity signs ----
    // scalar probability (FMUL + FFMA, no pairing MOVs), then sum/diff pair
    // tree for P_k = sum_r p[r]*(-1)^{parity(r>>k)} and T = sum p[r]
    float p[R];
#pragma unroll
    for (int r = 0; r < R; r++) {
        float xx, yy; unpack2(a[r], xx, yy);
        p[r] = fmaf(yy, yy, xx * xx);
    }
    float s1[16], d1[16];
#pragma unroll
    for (int k = 0; k < 16; k++) { s1[k] = p[2*k] + p[2*k+1]; d1[k] = p[2*k] - p[2*k+1]; }
    float P0 = 0.f;
#pragma unroll
    for (int k = 0; k < 16; k++) P0 += (__popc(k) & 1) ? -d1[k] : d1[k];
    float s2[8], d2[8];
#pragma unroll
    for (int k = 0; k < 8; k++) { s2[k] = s1[2*k] + s1[2*k+1]; d2[k] = s1[2*k] - s1[2*k+1]; }
    float P1 = 0.f;
#pragma unroll
    for (int k = 0; k < 8; k++) P1 += (__popc(k) & 1) ? -d2[k] : d2[k];
    float s3[4], d3[4];
#pragma unroll
    for (int k = 0; k < 4; k++) { s3[k] = s2[2*k] + s2[2*k+1]; d3[k] = s2[2*k] - s2[2*k+1]; }
    const float P2 = d3[0] - d3[1] - d3[2] + d3[3];
    const float s4a = s3[0] + s3[1], s4b = s3[2] + s3[3];
    const float P3 = (s3[0] - s3[1]) - (s3[2] - s3[3]);
    const float T  = s4a + s4b;
    const float P4 = s4a - s4b;

    const int pl = __popc(lane) & 1;
    float z[NQ];
    z[9] = pl ? -P0 : P0;
    z[8] = pl ? -P1 : P1;
    z[7] = pl ? -P2 : P2;
    z[6] = pl ? -P3 : P3;
    z[5] = pl ? -P4 : P4;
    z[4] = pl ? -T  : T;
    z[3] = (__popc(lane >> 1) & 1) ? -T : T;
    z[2] = (__popc(lane >> 2) & 1) ? -T : T;
    z[1] = (__popc(lane >> 3) & 1) ? -T : T;
    z[0] = (__popc(lane & 0xF) & 1) ? -P0 : P0;

#pragma unroll
    for (int q = 0; q < NQ; q++) {
#pragma unroll
        for (int o = 16; o > 0; o >>= 1)
            z[q] += __shfl_xor_sync(0xffffffffu, z[q], o);
    }
    if (lane == 0) {
#pragma unroll
        for (int q = 0; q < NQ; q++) out[b * NQ + q] = z[q] * Zsq;
    }
}

extern "C" void kernel_launch(void* const* d_in, const int* in_sizes, int n_in,
                              void* d_out, int out_size)
{
    const float* x = (const float*)d_in[0];       // (B, 10) float32
    const float* w = (const float*)d_in[1];       // (3, 10, 3) float32
    float* out = (float*)d_out;                   // (B, 10) float32
    const int B = in_sizes[0] / NQ;
    qnn_kernel<<<B / 2, NT>>>(x, w, out);
}